// round 1
// baseline (speedup 1.0000x reference)
#include <cuda_runtime.h>
#include <cstdint>

#define B_SIZE 2048
#define C_CH   129
#define T_LEN  200
#define BC     (B_SIZE * C_CH)     // 264192
#define KPAD   104                 // 13 * 8
#define NPADC  64                  // padded coef columns (60 re/im + mean + pad)
#define CSTRIDE 108                // coefT row stride in floats (bank-conflict-free)
#define TILE_S  72                 // epilogue tile row stride

// ---- device scratch (no allocation allowed) ----
__device__ float g_coefT[NPADC * CSTRIDE];  // [n][k], tf32-rounded
__device__ float g_avg[BC];
__device__ float g_max[BC];
__device__ float g_feats[BC * 4];           // (B, C*4) band features

__device__ __forceinline__ unsigned f2tf32(float v) {
    unsigned u; asm("cvt.rna.tf32.f32 %0, %1;" : "=r"(u) : "f"(v));
    return u;
}

// ============================================================
// Kernel 0: build DFT coefficient table (tf32-rounded)
// col n = 2j   -> w[k] *  cos(2*pi*(j+1)*k/100)   (Re)
// col n = 2j+1 -> w[k] * -sin(2*pi*(j+1)*k/100)   (Im)
// col 60       -> 1/100 (segment mean)
// ============================================================
__global__ void init_coef_kernel() {
    int idx = blockIdx.x * blockDim.x + threadIdx.x;
    if (idx >= NPADC * CSTRIDE) return;
    int n = idx / CSTRIDE, k = idx - n * CSTRIDE;
    float v = 0.0f;
    if (k < 100 && n < 61) {
        if (n == 60) {
            v = 0.01f;
        } else {
            int bin = (n >> 1) + 1;                 // 1..30
            int m = (k * bin) % 100;                // exact angle reduction
            float w = 0.5f - 0.5f * cospif((float)k / 50.0f);  // periodic hann
            float a = (float)m / 50.0f;             // angle in units of pi
            v = (n & 1) ? (-w * sinpif(a)) : (w * cospif(a));
        }
    }
    g_coefT[idx] = __uint_as_float(f2tf32(v));
}

// ============================================================
// Kernel 1: Welch band features + avg/max, via tf32 mma GEMM
// block = 16 (b,c) rows = 48 segment rows (M) x 64 cols (N) x 104 (K)
// 128 threads = 4 warps; warp w owns 3 M-frags x N-frags {2w, 2w+1}
// ============================================================
__global__ __launch_bounds__(128) void welch_kernel(const float* __restrict__ x) {
    __shared__ float xs[16 * 200 + 16];          // staged x rows (tf32-rounded), +pad
    __shared__ float cs[NPADC * CSTRIDE];        // coef tile; reused as 48x72 out tile
    __shared__ float fl[16][4];                  // per-(b,c) band sums

    const int tid  = threadIdx.x;
    const int lane = tid & 31;
    const int wrp  = tid >> 5;
    const int bc0  = blockIdx.x * 16;

    // stage coefficients (L1-resident after first block per SM)
    for (int i = tid; i < NPADC * CSTRIDE; i += 128) cs[i] = g_coefT[i];
    if (tid < 16) xs[16 * 200 + tid] = 0.0f;     // zero pad tail (read by K-pad lanes)

    // stage x rows; fused avg/max reduction (from full-precision values)
    for (int i = wrp; i < 16; i += 4) {
        const float* row = x + (size_t)(bc0 + i) * T_LEN;
        float s = 0.0f, mx = -3.4e38f;
        for (int c = lane; c < T_LEN; c += 32) {
            float v = row[c];
            s += v; mx = fmaxf(mx, v);
            xs[i * 200 + c] = __uint_as_float(f2tf32(v));
        }
        #pragma unroll
        for (int o = 16; o; o >>= 1) {
            s  += __shfl_down_sync(0xffffffffu, s, o);
            mx  = fmaxf(mx, __shfl_down_sync(0xffffffffu, mx, o));
        }
        if (lane == 0) { g_avg[bc0 + i] = s * (1.0f / 200.0f); g_max[bc0 + i] = mx; }
    }
    __syncthreads();

    const int g  = lane >> 2;    // groupID 0..7
    const int c4 = lane & 3;     // thread-in-group 0..3

    // A row base addresses: M row r -> (b,c)-local i = r/3, segment s = r%3
    int ab[3][2];
    #pragma unroll
    for (int mi = 0; mi < 3; mi++) {
        int r0 = 16 * mi + g;
        ab[mi][0] = (r0 / 3) * 200 + (r0 % 3) * 50;
        int r1 = r0 + 8;
        ab[mi][1] = (r1 / 3) * 200 + (r1 % 3) * 50;
    }
    // B bases: n = 16*wrp + 8*nn + g
    int bb[2];
    bb[0] = (16 * wrp +     g) * CSTRIDE;
    bb[1] = (16 * wrp + 8 + g) * CSTRIDE;

    float acc[3][2][4];
    #pragma unroll
    for (int mi = 0; mi < 3; mi++)
        #pragma unroll
        for (int nn = 0; nn < 2; nn++)
            #pragma unroll
            for (int q = 0; q < 4; q++) acc[mi][nn][q] = 0.0f;

    #pragma unroll
    for (int kk = 0; kk < 13; kk++) {
        const int k0 = kk * 8;
        unsigned b0[2], b1[2];
        #pragma unroll
        for (int nn = 0; nn < 2; nn++) {
            b0[nn] = __float_as_uint(cs[bb[nn] + k0 + c4]);
            b1[nn] = __float_as_uint(cs[bb[nn] + k0 + c4 + 4]);
        }
        #pragma unroll
        for (int mi = 0; mi < 3; mi++) {
            unsigned a0 = __float_as_uint(xs[ab[mi][0] + k0 + c4]);
            unsigned a1 = __float_as_uint(xs[ab[mi][1] + k0 + c4]);
            unsigned a2 = __float_as_uint(xs[ab[mi][0] + k0 + c4 + 4]);
            unsigned a3 = __float_as_uint(xs[ab[mi][1] + k0 + c4 + 4]);
            #pragma unroll
            for (int nn = 0; nn < 2; nn++) {
                asm volatile(
                    "mma.sync.aligned.m16n8k8.row.col.f32.tf32.tf32.f32 "
                    "{%0,%1,%2,%3}, {%4,%5,%6,%7}, {%8,%9}, {%0,%1,%2,%3};\n"
                    : "+f"(acc[mi][nn][0]), "+f"(acc[mi][nn][1]),
                      "+f"(acc[mi][nn][2]), "+f"(acc[mi][nn][3])
                    : "r"(a0), "r"(a1), "r"(a2), "r"(a3),
                      "r"(b0[nn]), "r"(b1[nn]));
            }
        }
    }
    __syncthreads();   // everyone done reading cs -> reuse as output tile

    float* tile = cs;  // 48 rows x TILE_S stride
    if (tid < 64) fl[tid >> 2][tid & 3] = 0.0f;
    #pragma unroll
    for (int mi = 0; mi < 3; mi++) {
        #pragma unroll
        for (int nn = 0; nn < 2; nn++) {
            int col = 16 * wrp + 8 * nn + 2 * c4;
            int r0 = 16 * mi + g;
            tile[r0 * TILE_S + col]           = acc[mi][nn][0];
            tile[r0 * TILE_S + col + 1]       = acc[mi][nn][1];
            tile[(r0 + 8) * TILE_S + col]     = acc[mi][nn][2];
            tile[(r0 + 8) * TILE_S + col + 1] = acc[mi][nn][3];
        }
    }
    __syncthreads();

    // PSD + band accumulation. bin-1 detrend fix: X1 += 25*m  (hann: W1 = -25)
    for (int idx = tid; idx < 48 * 30; idx += 128) {
        int r = idx / 30;
        int bin = idx - r * 30 + 1;                  // 1..30
        float re = tile[r * TILE_S + 2 * (bin - 1)];
        float im = tile[r * TILE_S + 2 * (bin - 1) + 1];
        if (bin == 1) re += 25.0f * tile[r * TILE_S + 60];
        float p = re * re + im * im;
        int i = r / 3;
        if (bin <= 4)               atomicAdd(&fl[i][0], p);   // delta 1..4
        if (bin >= 4 && bin <= 8)   atomicAdd(&fl[i][1], p);   // theta 4..8
        if (bin >= 8 && bin <= 13)  atomicAdd(&fl[i][2], p);   // alpha 8..13
        if (bin >= 13)              atomicAdd(&fl[i][3], p);   // beta 13..30
    }
    __syncthreads();

    if (tid < 64) {
        int i = tid >> 2, band = tid & 3;
        // 2 (one-sided) / (sfreq*win_sq_sum=3750) / 3 segs / band count
        const float norm[4] = { 2.0f / (11250.0f * 4.0f), 2.0f / (11250.0f * 5.0f),
                                2.0f / (11250.0f * 6.0f), 2.0f / (11250.0f * 18.0f) };
        g_feats[(size_t)(bc0 + i) * 4 + band] = fl[i][band] * norm[band];
    }
}

// ============================================================
// Kernel 2: attention + time feature + freq MLP + head, fused
// block = 8 batch rows, 256 threads
// ============================================================
__global__ __launch_bounds__(256) void mlp_kernel(
    const float* __restrict__ w_att1, const float* __restrict__ w_att2,
    const float* __restrict__ w_bb,   const float* __restrict__ b_bb,
    const float* __restrict__ w_fe1,  const float* __restrict__ b_fe1,
    const float* __restrict__ w_fe2,  const float* __restrict__ b_fe2,
    const float* __restrict__ w_h1,   const float* __restrict__ b_h1,
    const float* __restrict__ w_h2,   const float* __restrict__ b_h2,
    const float* __restrict__ w_h3,   const float* __restrict__ b_h3,
    float* __restrict__ out)
{
    __shared__ float a_s[8 * 129];
    __shared__ float m_s[8 * 129];        // later reused as h2 output (8*64)
    __shared__ float hpart[8][16][2];
    __shared__ float hsum[8][16];
    __shared__ float f_s[8 * 516];
    __shared__ float f1_s[8 * 128];       // fe1 out; later reused as h1 out
    __shared__ float hcat[8 * 128];       // [time_feat | freq]

    const int tid = threadIdx.x;
    const int b0 = blockIdx.x * 8;

    for (int idx = tid; idx < 8 * 129; idx += 256) {
        int r = idx / 129, c = idx - r * 129;
        a_s[idx] = g_avg[(size_t)(b0 + r) * 129 + c];
        m_s[idx] = g_max[(size_t)(b0 + r) * 129 + c];
    }
    for (int idx = tid; idx < 8 * 516; idx += 256) {
        int r = idx / 516, i = idx - r * 516;
        f_s[idx] = g_feats[(size_t)(b0 + r) * 516 + i];
    }
    __syncthreads();

    {   // attention hidden: relu(v @ w_att1), v in {avg, max}
        int r = tid >> 5, h = (tid >> 1) & 15, src = tid & 1;
        const float* v = src ? (m_s + r * 129) : (a_s + r * 129);
        float d = 0.0f;
        for (int c = 0; c < 129; c++) d += v[c] * w_att1[c * 16 + h];
        hpart[r][h][src] = fmaxf(d, 0.0f);
    }
    __syncthreads();
    if (tid < 128) {
        int r = tid >> 4, h = tid & 15;
        hsum[r][h] = hpart[r][h][0] + hpart[r][h][1];
    }
    __syncthreads();

    // att = sigmoid(hsum @ w_att2); pooled = avg * att (in place)
    for (int idx = tid; idx < 8 * 129; idx += 256) {
        int r = idx / 129, c = idx - r * 129;
        float s = 0.0f;
        #pragma unroll
        for (int h = 0; h < 16; h++) s += hsum[r][h] * w_att2[h * 129 + c];
        float att = 1.0f / (1.0f + expf(-s));
        a_s[idx] = a_s[idx] * att;
    }
    __syncthreads();

    // time_feat = relu(pooled @ w_bb + b_bb) -> hcat[:, 0:64]
    for (int idx = tid; idx < 8 * 64; idx += 256) {
        int r = idx >> 6, j = idx & 63;
        float d = b_bb[j];
        for (int c = 0; c < 129; c++) d += a_s[r * 129 + c] * w_bb[c * 64 + j];
        hcat[r * 128 + j] = fmaxf(d, 0.0f);
    }
    // fe1 = relu(feats @ w_fe1 + b)  (independent of above)
    for (int idx = tid; idx < 8 * 128; idx += 256) {
        int r = idx >> 7, j = idx & 127;
        float d = b_fe1[j];
        for (int i = 0; i < 516; i++) d += f_s[r * 516 + i] * w_fe1[i * 128 + j];
        f1_s[idx] = fmaxf(d, 0.0f);
    }
    __syncthreads();
    // fe2 -> hcat[:, 64:128]
    for (int idx = tid; idx < 8 * 64; idx += 256) {
        int r = idx >> 6, j = idx & 63;
        float d = b_fe2[j];
        #pragma unroll 4
        for (int i = 0; i < 128; i++) d += f1_s[r * 128 + i] * w_fe2[i * 64 + j];
        hcat[r * 128 + 64 + j] = fmaxf(d, 0.0f);
    }
    __syncthreads();
    // h1 -> f1_s (reuse)
    for (int idx = tid; idx < 8 * 128; idx += 256) {
        int r = idx >> 7, j = idx & 127;
        float d = b_h1[j];
        #pragma unroll 4
        for (int i = 0; i < 128; i++) d += hcat[r * 128 + i] * w_h1[i * 128 + j];
        f1_s[idx] = fmaxf(d, 0.0f);
    }
    __syncthreads();
    // h2 -> m_s (reuse)
    float* h2out = m_s;
    for (int idx = tid; idx < 8 * 64; idx += 256) {
        int r = idx >> 6, j = idx & 63;
        float d = b_h2[j];
        #pragma unroll 4
        for (int i = 0; i < 128; i++) d += f1_s[r * 128 + i] * w_h2[i * 64 + j];
        h2out[idx] = fmaxf(d, 0.0f);
    }
    __syncthreads();
    if (tid < 8) {
        float d = b_h3[0];
        #pragma unroll 8
        for (int i = 0; i < 64; i++) d += h2out[tid * 64 + i] * w_h3[i];
        out[b0 + tid] = d;
    }
}

// ============================================================
extern "C" void kernel_launch(void* const* d_in, const int* in_sizes, int n_in,
                              void* d_out, int out_size) {
    (void)in_sizes; (void)n_in; (void)out_size;
    const float* x = (const float*)d_in[0];

    init_coef_kernel<<<(NPADC * CSTRIDE + 255) / 256, 256>>>();
    welch_kernel<<<BC / 16, 128>>>(x);
    mlp_kernel<<<B_SIZE / 8, 256>>>(
        (const float*)d_in[1],  (const float*)d_in[2],
        (const float*)d_in[3],  (const float*)d_in[4],
        (const float*)d_in[5],  (const float*)d_in[6],
        (const float*)d_in[7],  (const float*)d_in[8],
        (const float*)d_in[9],  (const float*)d_in[10],
        (const float*)d_in[11], (const float*)d_in[12],
        (const float*)d_in[13], (const float*)d_in[14],
        (float*)d_out);
}